// round 5
// baseline (speedup 1.0000x reference)
#include <cuda_runtime.h>
#include <stdint.h>

// Hash constants: ((c+1) * PIS[c]) for c = 0..7 (exact 64-bit products).
// tidx = (idx ^ PP[c]) & (TABLE_SIZE-1); valid since idx >= 0, TABLE_SIZE = 2^19.
__constant__ unsigned long long c_pp[8] = {
    774363409ull, 5308871522ull, 2416379583ull, 400000028ull,
    1671816955ull, 8006180478ull, 5140543849ull, 17074907144ull
};

#define TABLE_MASK 0x7FFFFull
#define NRED 32
#define FULLM 0xffffffffu

static __device__ int g_partial[NRED];

// ---------------------------------------------------------------------------
// Kernel 1: per-block max over depth -> g_partial[blockIdx]
// ---------------------------------------------------------------------------
__global__ void depth_reduce_kernel(const int* __restrict__ depth, int n) {
    int m = 0;
    for (int i = blockIdx.x * blockDim.x + threadIdx.x; i < n;
         i += gridDim.x * blockDim.x)
        m = max(m, depth[i]);
    #pragma unroll
    for (int s = 16; s > 0; s >>= 1)
        m = max(m, __shfl_xor_sync(FULLM, m, s));
    __shared__ int sm[32];
    int w = threadIdx.x >> 5;
    if ((threadIdx.x & 31) == 0) sm[w] = m;
    __syncthreads();
    if (threadIdx.x == 0) {
        int nw = (blockDim.x + 31) >> 5;
        int mm = sm[0];
        for (int i = 1; i < nw; i++) mm = max(mm, sm[i]);
        g_partial[blockIdx.x] = mm;
    }
}

// ---------------------------------------------------------------------------
// Kernel 2: main encoding. Block = one ray (256 threads). Warp w = level l.
// Features loaded DIRECTLY into registers: each emb row (64B, 64B-aligned)
// sits in one 128B line, so a warp-broadcast LDG.128 per corner costs one
// wavefront — same line traffic as the old smem gather but no STS/LDS.
// Two batches of 4 corners (MLP=4) bound register pressure.
// inp coords staged once in smem, read via conflict-free scalar LDS.
// ---------------------------------------------------------------------------
__global__ void __launch_bounds__(256) nbvh_main_kernel(
    const float* __restrict__ inp,          // [R,16,3]
    const int*   __restrict__ history,      // [R,64]
    const float* __restrict__ nodes_min,    // [N,3]
    const float* __restrict__ nodes_extent, // [N,3]
    const float* __restrict__ emb,          // [524288,16]
    float* __restrict__ out)                // [R, 8*16*16]
{
    __shared__ float s_inp[48];
    __shared__ int   s_activeL;

    const int tid  = threadIdx.x;
    const int w    = tid >> 5;       // level l
    const int lane = tid & 31;
    const int r    = blockIdx.x;

    // warp 0: parallel reduce of the 32 partials
    if (tid < 32) {
        int m = g_partial[tid];
        #pragma unroll
        for (int s = 16; s > 0; s >>= 1)
            m = max(m, __shfl_xor_sync(FULLM, m, s));
        if (tid == 0) s_activeL = (m < 8) ? m : 8;
    }
    // warp 1: stage this ray's 48 coords (12 float4)
    if (tid >= 32 && tid < 44) {
        reinterpret_cast<float4*>(s_inp)[tid - 32] =
            reinterpret_cast<const float4*>(inp + (size_t)r * 48)[tid - 32];
    }

    const int idx = history[r * 64 + w];

    // node box (uniform within warp -> 1 wavefront per load)
    const float pmx = nodes_min[(size_t)idx * 3 + 0];
    const float pmy = nodes_min[(size_t)idx * 3 + 1];
    const float pmz = nodes_min[(size_t)idx * 3 + 2];
    const float rex = __fdividef(1.0f, nodes_extent[(size_t)idx * 3 + 0]);
    const float rey = __fdividef(1.0f, nodes_extent[(size_t)idx * 3 + 1]);
    const float rez = __fdividef(1.0f, nodes_extent[(size_t)idx * 3 + 2]);

    __syncthreads();

    const float act  = (w < s_activeL) ? 1.0f : 0.0f;
    const int   p_lo = lane >> 2;     // points p_lo and p_lo+8
    const int   dsub = lane & 3;      // float4 dim group

    // weight factors: P[half][4] xy-products, Z[half][2] z-terms (act folded)
    float P[2][4], Z[2][2];
    #pragma unroll
    for (int half = 0; half < 2; half++) {
        const int p = p_lo + 8 * half;
        float x = fminf(fmaxf((s_inp[p * 3 + 0] - pmx) * rex, 0.0f), 1.0f);
        float y = fminf(fmaxf((s_inp[p * 3 + 1] - pmy) * rey, 0.0f), 1.0f);
        float z = fminf(fmaxf((s_inp[p * 3 + 2] - pmz) * rez, 0.0f), 1.0f);
        const float ix = 1.0f - x, iy = 1.0f - y;
        P[half][0] = ix * iy;  P[half][1] = x * iy;
        P[half][2] = ix * y;   P[half][3] = x * y;
        Z[half][0] = (1.0f - z) * act;   // iz terms
        Z[half][1] = z * act;            // z terms
    }

    const float4* e4 = reinterpret_cast<const float4*>(emb);
    const unsigned uidx = (unsigned)idx;

    float4 alo = make_float4(0.f, 0.f, 0.f, 0.f);
    float4 ahi = make_float4(0.f, 0.f, 0.f, 0.f);

    // corner weight composition: w_c = P[pi[c]] * Z[zi[c]]
    //   c:  0  1  2  3  4  5  6  7
    //  pi:  0  1  2  0  1  2  3  3
    //  zi:  0  0  0  1  1  1  0  1
#define ACC(f, PI, ZI)                                            \
    {                                                             \
        const float wl = P[0][PI] * Z[0][ZI];                     \
        const float wh = P[1][PI] * Z[1][ZI];                     \
        alo.x = fmaf(wl, (f).x, alo.x);                           \
        alo.y = fmaf(wl, (f).y, alo.y);                           \
        alo.z = fmaf(wl, (f).z, alo.z);                           \
        alo.w = fmaf(wl, (f).w, alo.w);                           \
        ahi.x = fmaf(wh, (f).x, ahi.x);                           \
        ahi.y = fmaf(wh, (f).y, ahi.y);                           \
        ahi.z = fmaf(wh, (f).z, ahi.z);                           \
        ahi.w = fmaf(wh, (f).w, ahi.w);                           \
    }
#define TIX(c) ((size_t)(unsigned)(((unsigned long long)uidx ^ c_pp[c]) \
                                   & TABLE_MASK))

    {   // batch 0: corners 0..3, MLP=4
        const float4 f0 = __ldg(e4 + TIX(0) * 4 + dsub);
        const float4 f1 = __ldg(e4 + TIX(1) * 4 + dsub);
        const float4 f2 = __ldg(e4 + TIX(2) * 4 + dsub);
        const float4 f3 = __ldg(e4 + TIX(3) * 4 + dsub);
        ACC(f0, 0, 0); ACC(f1, 1, 0); ACC(f2, 2, 0); ACC(f3, 0, 1);
    }
    asm volatile("" ::: "memory");   // keep batch 1 loads below batch 0 use
    {   // batch 1: corners 4..7, MLP=4
        const float4 f4 = __ldg(e4 + TIX(4) * 4 + dsub);
        const float4 f5 = __ldg(e4 + TIX(5) * 4 + dsub);
        const float4 f6 = __ldg(e4 + TIX(6) * 4 + dsub);
        const float4 f7 = __ldg(e4 + TIX(7) * 4 + dsub);
        ACC(f4, 1, 1); ACC(f5, 2, 1); ACC(f6, 3, 0); ACC(f7, 3, 1);
    }
#undef ACC
#undef TIX

    // Output tile for (r, l): 64 float4; two contiguous 512B warp stores.
    float4* o = reinterpret_cast<float4*>(out) + ((size_t)r * 8 + w) * 64;
    o[lane]      = alo;
    o[32 + lane] = ahi;
}

// ---------------------------------------------------------------------------
extern "C" void kernel_launch(void* const* d_in, const int* in_sizes, int n_in,
                              void* d_out, int out_size) {
    const float* inp     = (const float*)d_in[0];
    const int*   history = (const int*)d_in[1];
    const int*   depth   = (const int*)d_in[2];
    const float* nmin    = (const float*)d_in[3];
    const float* next    = (const float*)d_in[4];
    const float* emb     = (const float*)d_in[5];
    float*       out     = (float*)d_out;

    const int R = in_sizes[2];   // number of rays (= depth element count)

    depth_reduce_kernel<<<NRED, 256>>>(depth, R);
    nbvh_main_kernel<<<R, 256>>>(inp, history, nmin, next, emb, out);
}

// round 6
// speedup vs baseline: 1.1811x; 1.1811x over previous
#include <cuda_runtime.h>
#include <stdint.h>

// Hash constants: ((c+1) * PIS[c]) for c = 0..7 (exact 64-bit products).
// tidx = (idx ^ PP[c]) & (TABLE_SIZE-1); valid since idx >= 0, TABLE_SIZE = 2^19.
__constant__ unsigned long long c_pp[8] = {
    774363409ull, 5308871522ull, 2416379583ull, 400000028ull,
    1671816955ull, 8006180478ull, 5140543849ull, 17074907144ull
};

#define TABLE_MASK 0x7FFFFull
#define NRED 32
#define FULLM 0xffffffffu

static __device__ int g_partial[NRED];

// ---------------------------------------------------------------------------
// Kernel 1: per-block max over depth -> g_partial[blockIdx]
// ---------------------------------------------------------------------------
__global__ void depth_reduce_kernel(const int* __restrict__ depth, int n) {
    int m = 0;
    for (int i = blockIdx.x * blockDim.x + threadIdx.x; i < n;
         i += gridDim.x * blockDim.x)
        m = max(m, depth[i]);
    #pragma unroll
    for (int s = 16; s > 0; s >>= 1)
        m = max(m, __shfl_xor_sync(FULLM, m, s));
    __shared__ int sm[32];
    int w = threadIdx.x >> 5;
    if ((threadIdx.x & 31) == 0) sm[w] = m;
    __syncthreads();
    if (threadIdx.x == 0) {
        int nw = (blockDim.x + 31) >> 5;
        int mm = sm[0];
        for (int i = 1; i < nw; i++) mm = max(mm, sm[i]);
        g_partial[blockIdx.x] = mm;
    }
}

// ---------------------------------------------------------------------------
// Kernel 2: main encoding — R2 chassis (proven fastest) + inp smem staging
// + register-lean factorized weights.
// Block = one ray (256 threads). Warp w = level l (0..7).
// Per warp: gather 8 corner feature rows (8 x 16 fp32 = 512B) into smem once,
// then each lane produces two float4 output slices (two points, same dim
// group) so both warp STG.128s are fully contiguous 512B stores.
// ---------------------------------------------------------------------------
__global__ void __launch_bounds__(256, 8) nbvh_main_kernel(
    const float* __restrict__ inp,          // [R,16,3]
    const int*   __restrict__ history,      // [R,64]
    const float* __restrict__ nodes_min,    // [N,3]
    const float* __restrict__ nodes_extent, // [N,3]
    const float* __restrict__ emb,          // [524288,16]
    float* __restrict__ out)                // [R, 8*16*16]
{
    __shared__ float4 sfeat[8][32];   // [warp][corner*4 + dim_group]
    __shared__ float  s_inp[48];      // this ray's 16x3 coords
    __shared__ int    s_activeL;

    const int tid  = threadIdx.x;
    const int w    = tid >> 5;       // level l
    const int lane = tid & 31;
    const int r    = blockIdx.x;

    // warp 0: parallel reduce of the 32 partials
    if (tid < 32) {
        int m = g_partial[tid];
        #pragma unroll
        for (int s = 16; s > 0; s >>= 1)
            m = max(m, __shfl_xor_sync(FULLM, m, s));
        if (tid == 0) s_activeL = (m < 8) ? m : 8;
    }
    // warp 1: stage this ray's 48 coords (12 float4, coalesced)
    if (tid >= 32 && tid < 44) {
        reinterpret_cast<float4*>(s_inp)[tid - 32] =
            reinterpret_cast<const float4*>(inp + (size_t)r * 48)[tid - 32];
    }

    const int idx = history[r * 64 + w];

    // Gather features: lane -> (corner = lane>>2, float4 sub = lane&3)
    {
        const int c   = lane >> 2;
        const int sub = lane & 3;
        unsigned tix =
            (unsigned)(((unsigned long long)(unsigned)idx ^ c_pp[c]) & TABLE_MASK);
        sfeat[w][lane] =
            reinterpret_cast<const float4*>(emb)[(size_t)tix * 4 + sub];
    }

    // Node box (uniform within warp -> 1 wavefront per load)
    const float pmx = nodes_min[(size_t)idx * 3 + 0];
    const float pmy = nodes_min[(size_t)idx * 3 + 1];
    const float pmz = nodes_min[(size_t)idx * 3 + 2];
    const float rex = __fdividef(1.0f, nodes_extent[(size_t)idx * 3 + 0]);
    const float rey = __fdividef(1.0f, nodes_extent[(size_t)idx * 3 + 1]);
    const float rez = __fdividef(1.0f, nodes_extent[(size_t)idx * 3 + 2]);

    __syncthreads();   // sfeat + s_inp + s_activeL visible

    const float act  = (w < s_activeL) ? 1.0f : 0.0f;
    const int   p_lo = lane >> 2;     // points p_lo and p_lo+8
    const int   dsub = lane & 3;      // float4 dim group

    // Factorized weights: P[half][4] xy-products, Z[half][2] z-terms (act in)
    float P[2][4], Z[2][2];
    #pragma unroll
    for (int half = 0; half < 2; half++) {
        const int p = p_lo + 8 * half;
        float x = fminf(fmaxf((s_inp[p * 3 + 0] - pmx) * rex, 0.0f), 1.0f);
        float y = fminf(fmaxf((s_inp[p * 3 + 1] - pmy) * rey, 0.0f), 1.0f);
        float z = fminf(fmaxf((s_inp[p * 3 + 2] - pmz) * rez, 0.0f), 1.0f);
        const float ix = 1.0f - x, iy = 1.0f - y;
        P[half][0] = ix * iy;  P[half][1] = x * iy;
        P[half][2] = ix * y;   P[half][3] = x * y;
        Z[half][0] = (1.0f - z) * act;
        Z[half][1] = z * act;
    }

    float4 alo = make_float4(0.f, 0.f, 0.f, 0.f);
    float4 ahi = make_float4(0.f, 0.f, 0.f, 0.f);

    // corner -> (P index, Z index):
    //   c:  0  1  2  3  4  5  6  7
    //  pi:  0  1  2  0  1  2  3  3
    //  zi:  0  0  0  1  1  1  0  1
    const int pi_[8] = {0, 1, 2, 0, 1, 2, 3, 3};
    const int zi_[8] = {0, 0, 0, 1, 1, 1, 0, 1};
    #pragma unroll
    for (int c = 0; c < 8; c++) {
        const float4 f  = sfeat[w][c * 4 + dsub];   // broadcast LDS.128
        const float  wl = P[0][pi_[c]] * Z[0][zi_[c]];
        const float  wh = P[1][pi_[c]] * Z[1][zi_[c]];
        alo.x = fmaf(wl, f.x, alo.x);
        alo.y = fmaf(wl, f.y, alo.y);
        alo.z = fmaf(wl, f.z, alo.z);
        alo.w = fmaf(wl, f.w, alo.w);
        ahi.x = fmaf(wh, f.x, ahi.x);
        ahi.y = fmaf(wh, f.y, ahi.y);
        ahi.z = fmaf(wh, f.z, ahi.z);
        ahi.w = fmaf(wh, f.w, ahi.w);
    }

    // Output tile for (r, l): 64 float4; two contiguous 512B warp stores.
    float4* o = reinterpret_cast<float4*>(out) + ((size_t)r * 8 + w) * 64;
    o[lane]      = alo;
    o[32 + lane] = ahi;
}

// ---------------------------------------------------------------------------
extern "C" void kernel_launch(void* const* d_in, const int* in_sizes, int n_in,
                              void* d_out, int out_size) {
    const float* inp     = (const float*)d_in[0];
    const int*   history = (const int*)d_in[1];
    const int*   depth   = (const int*)d_in[2];
    const float* nmin    = (const float*)d_in[3];
    const float* next    = (const float*)d_in[4];
    const float* emb     = (const float*)d_in[5];
    float*       out     = (float*)d_out;

    const int R = in_sizes[2];   // number of rays (= depth element count)

    depth_reduce_kernel<<<NRED, 256>>>(depth, R);
    nbvh_main_kernel<<<R, 256>>>(inp, history, nmin, next, emb, out);
}